// round 16
// baseline (speedup 1.0000x reference)
#include <cuda_runtime.h>
#include <cuda_fp16.h>
#include <math_constants.h>
#include <cstdint>

// ---------------- problem constants ----------------
#define B_     32
#define S_     64
#define E_     128
#define TSTEP  256
#define VOCAB  32000
#define ROWS   8192
#define NCHUNK 250            // vocab chunks of 128
#define GRP    10             // chunks per work unit (R10 proven)
#define NGRP   25             // units per mtile
#define NUNITS 1600           // 64 mtiles * 25
#define NCTA   148
#define NSLOT  (NGRP*4)       // (group, warp_n) partial slots
#define L2E    1.4426950408889634f

// ---------------- scratch ----------------
__device__ float    g_xtran [B_*S_*S_];
__device__ float    g_A     [B_*TSTEP*S_];
__device__ float    g_zs    [ROWS*E_];
__device__ float    g_bl2   [VOCAB];             // bias*L2E + (127 - 30*L2E)
__device__ __align__(16) unsigned short g_w16[VOCAB*E_];
__device__ __align__(16) unsigned short g_a16[ROWS*S_];          // A matrix fp16 [row t][s]
__device__ __align__(16) unsigned short g_xw16[(size_t)B_*VOCAB*S_]; // xv·W^T fp16, tile layout
__device__ __align__(16) float g_epsG[NSLOT*ROWS];
__device__ float    g_tg [ROWS];

// ---------------- helpers ----------------
__device__ __forceinline__ uint32_t smem_u32b(const void* p) {
    uint32_t a;
    asm("{ .reg .u64 t; cvta.to.shared.u64 t, %1; cvt.u32.u64 %0, t; }" : "=r"(a) : "l"(p));
    return a;
}
__device__ __forceinline__ void cpa16(uint32_t dst, const void* src) {
    asm volatile("cp.async.cg.shared.global [%0], [%1], 16;" :: "r"(dst), "l"(src));
}
#define CP_COMMIT() asm volatile("cp.async.commit_group;" ::: "memory")
#define CP_WAIT1()  asm volatile("cp.async.wait_group 1;" ::: "memory")
#define CP_WAIT0()  asm volatile("cp.async.wait_group 0;" ::: "memory")

__device__ __forceinline__ void ldm_x4(uint32_t addr, uint32_t& r0, uint32_t& r1, uint32_t& r2, uint32_t& r3) {
    asm volatile("ldmatrix.sync.aligned.m8n8.x4.shared.b16 {%0,%1,%2,%3}, [%4];"
        : "=r"(r0), "=r"(r1), "=r"(r2), "=r"(r3) : "r"(addr));
}
__device__ __forceinline__ void ldm_x2(uint32_t addr, uint32_t& r0, uint32_t& r1) {
    asm volatile("ldmatrix.sync.aligned.m8n8.x2.shared.b16 {%0,%1}, [%2];"
        : "=r"(r0), "=r"(r1) : "r"(addr));
}
// fp16-accumulate HMMA (2 result regs)
__device__ __forceinline__ void mma16816h(uint32_t* d, const uint32_t* a, const uint32_t* b) {
    asm volatile("mma.sync.aligned.m16n8k16.row.col.f16.f16.f16.f16 "
        "{%0,%1}, {%2,%3,%4,%5}, {%6,%7}, {%0,%1};"
        : "+r"(d[0]), "+r"(d[1])
        : "r"(a[0]), "r"(a[1]), "r"(a[2]), "r"(a[3]), "r"(b[0]), "r"(b[1]));
}

typedef unsigned long long u64t;
__device__ __forceinline__ u64t pk2(float lo, float hi) {
    u64t r; asm("mov.b64 %0, {%1, %2};" : "=l"(r) : "f"(lo), "f"(hi)); return r;
}
__device__ __forceinline__ u64t fma2v(u64t a, u64t b, u64t c) {
    u64t r; asm volatile("fma.rn.f32x2 %0, %1, %2, %3;" : "=l"(r) : "l"(a), "l"(b), "l"(c)); return r;
}
__device__ __forceinline__ u64t h2f2(uint32_t h) {
    __half2 hh = *(__half2*)&h;
    float2 f = __half22float2(hh);
    u64t r; asm("mov.b64 %0, {%1, %2};" : "=l"(r) : "f"(f.x), "f"(f.y));
    return r;
}

struct ExpC {
    u64t L2E2, MG2, NEG1, C4, C3, C2, C1, ONE2;
};
// packed exp(l-30) accumulate; bl2 pre-biased: bias*L2E + (127 - 30*L2E)
__device__ __forceinline__ void expacc2(u64t acc, u64t bl2, const ExpC& K, u64t& rs) {
    u64t y = fma2v(acc, K.L2E2, bl2);
    u64t t = fma2v(y, K.ONE2, K.MG2);        // y + magic
    u64t n = fma2v(K.MG2, K.NEG1, t);        // t - magic
    u64t f = fma2v(n, K.NEG1, y);            // y - n
    u64t p = fma2v(K.C4, f, K.C3);
    p = fma2v(p, f, K.C2);
    p = fma2v(p, f, K.C1);
    p = fma2v(p, f, K.ONE2);
    uint32_t t0, t1;
    asm("mov.b64 {%0, %1}, %2;" : "=r"(t0), "=r"(t1) : "l"(t));
    t0 <<= 23; t1 <<= 23;
    u64t sc; asm("mov.b64 %0, {%1, %2};" : "=l"(sc) : "r"(t0), "r"(t1));
    rs = fma2v(p, sc, rs);
}

// ================= Kernel A12: scores + softmax + att0 (fused) =================
#define KA12_SMEM ((8256 + 4160) * 4)
__global__ __launch_bounds__(256) void kA12(const float* __restrict__ latent,
                                            const int* __restrict__ zi) {
    extern __shared__ float s[];
    float* xkS = s;            // 64 x 129
    float* scS = s + 8256;     // 64 x 65
    __shared__ float smv[64];
    int b = blockIdx.x, tid = threadIdx.x;
    const float* xq = latent + (size_t)zi[(b >> 2)]     * 32768 + (size_t)(b & 3) * 8192;
    const float* xk = latent + (size_t)zi[8 + (b >> 2)] * 32768 + (size_t)(b & 3) * 8192;

    for (int idx = tid; idx < 8192; idx += 256)
        xkS[(idx >> 7) * 129 + (idx & 127)] = __ldg(xk + idx);
    __syncthreads();

    int t = tid & 63, sg = tid >> 6;
    for (int i = 0; i < 16; i++) {
        int ss = sg + 4 * i;
        float a0 = 0.f, a1 = 0.f, a2 = 0.f, a3 = 0.f;
        const float4* qp = (const float4*)(xq + ss * 128);
        #pragma unroll 8
        for (int e4 = 0; e4 < 32; e4++) {
            float4 q = __ldg(qp + e4);
            const float* kp = &xkS[t * 129 + e4 * 4];
            a0 = fmaf(q.x, kp[0], a0);
            a1 = fmaf(q.y, kp[1], a1);
            a2 = fmaf(q.z, kp[2], a2);
            a3 = fmaf(q.w, kp[3], a3);
        }
        scS[ss * 65 + t] = ((a0 + a1) + (a2 + a3)) * 0.08838834764831843f;
    }
    __syncthreads();

    if (tid < 64) {
        float mx = -CUDART_INF_F;
        for (int ss = 0; ss < 64; ss++) mx = fmaxf(mx, scS[ss * 65 + tid]);
        float sum = 0.f;
        for (int ss = 0; ss < 64; ss++) {
            float e = __expf(scS[ss * 65 + tid] - mx);
            scS[ss * 65 + tid] = e;
            sum += e;
        }
        float inv = 1.f / sum;
        for (int ss = 0; ss < 64; ss++)
            g_xtran[b * 4096 + ss * 64 + tid] = scS[ss * 65 + tid] * inv;
    }

    const float* ip = latent + (size_t)zi[24 + (b >> 2)] * 32768 + (size_t)(b & 3) * 8192;
    float xi = 0.f;
    if (tid < 64) { xi = __ldg(ip + tid * 128); smv[tid] = xi; }
    __syncthreads();
    float m2 = -CUDART_INF_F;
    if (tid < 64) { for (int ss = 0; ss < 64; ss++) m2 = fmaxf(m2, smv[ss]); }
    float e2 = (tid < 64) ? __expf(xi - m2) : 0.f;
    __syncthreads();
    if (tid < 64) smv[tid] = e2;
    __syncthreads();
    if (tid < 64) {
        float su = 0.f;
        for (int ss = 0; ss < 64; ss++) su += smv[ss];
        g_A[(size_t)b * 16384 + tid] = e2 / su;   // A[0] = att0
    }
}

// ---- 64-dot with 8 independent accumulator chains ----
__device__ __forceinline__ float dot64x(const float* __restrict__ row, const float* mcol) {
    float a0=0.f,a1=0.f,a2=0.f,a3=0.f,a4=0.f,a5=0.f,a6=0.f,a7=0.f;
    #pragma unroll
    for (int ss = 0; ss < 64; ss += 8) {
        float4 x = *(const float4*)&row[ss];
        float4 y = *(const float4*)&row[ss + 4];
        a0 = fmaf(x.x, mcol[ss+0], a0);
        a1 = fmaf(x.y, mcol[ss+1], a1);
        a2 = fmaf(x.z, mcol[ss+2], a2);
        a3 = fmaf(x.w, mcol[ss+3], a3);
        a4 = fmaf(y.x, mcol[ss+4], a4);
        a5 = fmaf(y.y, mcol[ss+5], a5);
        a6 = fmaf(y.z, mcol[ss+6], a6);
        a7 = fmaf(y.w, mcol[ss+7], a7);
    }
    return ((a0 + a1) + (a2 + a3)) + ((a4 + a5) + (a6 + a7));
}

// ================= Kernel B1v3: log-doubling scan (R10 proven) =================
#define KB1_SMEM ((4352*2 + 16384) * 4)
__global__ __launch_bounds__(512) void kB1v3() {
    extern __shared__ float s[];
    float* M0 = s;
    float* M1 = s + 4352;
    float* A  = s + 8704;
    int b = blockIdx.x, tid = threadIdx.x;
    int col = tid & 63, rg = tid >> 6;

    for (int i = tid; i < 4096; i += 512)
        M0[(i >> 6) * 68 + (i & 63)] = g_xtran[b * 4096 + i];
    if (tid < 64) A[tid] = g_A[(size_t)b * 16384 + tid];
    __syncthreads();

    float* Mp = M0; float* Mq = M1;
    int cur = 1;
    #pragma unroll 1
    for (int it = 0; it < 8; it++) {
        float mcol[64];
        #pragma unroll
        for (int ss = 0; ss < 64; ss++) mcol[ss] = Mp[ss * 68 + col];
        if (it < 7) {
            #pragma unroll 2
            for (int r = rg; r < 64; r += 8)
                Mq[r * 68 + col] = dot64x(Mp + r * 68, mcol);
        }
        #pragma unroll 2
        for (int r = rg; r < cur; r += 8)
            A[(cur + r) * 64 + col] = dot64x(A + r * 64, mcol);
        __syncthreads();
        float* t = Mp; Mp = Mq; Mq = t;
        cur <<= 1;
    }
    for (int i = tid; i < 4096; i += 512) {
        float4 v = *(const float4*)&A[i * 4];
        *(float4*)&g_A[(size_t)b * 16384 + (size_t)i * 4] = v;
    }
}

// ================= Kernel B2: zs = A * xv (for kT), + A fp16 convert =================
__global__ __launch_bounds__(256) void kB2(const float* __restrict__ latent, const int* __restrict__ zi) {
    __shared__ float As[2048];
    __shared__ float xvS[8192];
    int b = blockIdx.x >> 3, tb = blockIdx.x & 7;
    int tid = threadIdx.x;
    const float* xv = latent + (size_t)zi[16 + (b >> 2)] * 32768 + (size_t)(b & 3) * 8192;
    for (int i = tid; i < 8192; i += 256) xvS[i] = __ldg(xv + i);
    for (int i = tid; i < 2048; i += 256) As[i] = g_A[(size_t)(b * 256 + tb * 32) * 64 + i];
    __syncthreads();
    // A fp16 convert (rows b*256+tb*32 .. +32)
    for (int i = tid; i < 2048; i += 256)
        g_a16[(size_t)(b * 256 + tb * 32) * 64 + i] = __half_as_ushort(__float2half(As[i]));
    int e = tid & 127, h = tid >> 7;
    for (int i = 0; i < 16; i++) {
        int tl = h * 16 + i;
        float a0 = 0.f, a1 = 0.f, a2 = 0.f, a3 = 0.f;
        #pragma unroll
        for (int s2 = 0; s2 < 64; s2 += 4) {
            a0 = fmaf(As[tl * 64 + s2 + 0], xvS[(s2 + 0) * 128 + e], a0);
            a1 = fmaf(As[tl * 64 + s2 + 1], xvS[(s2 + 1) * 128 + e], a1);
            a2 = fmaf(As[tl * 64 + s2 + 2], xvS[(s2 + 2) * 128 + e], a2);
            a3 = fmaf(As[tl * 64 + s2 + 3], xvS[(s2 + 3) * 128 + e], a3);
        }
        float acc = (a0 + a1) + (a2 + a3);
        g_zs[((size_t)b * 256 + tb * 32 + tl) * 128 + e] = acc;
    }
}

// ================= Kernel Wc: vocab fp16 + bl2 + g_epsG zero =================
__global__ __launch_bounds__(256) void kWc(const float* __restrict__ vw,
                                           const float* __restrict__ vb) {
    int t = blockIdx.x * 256 + threadIdx.x;
    size_t i = (size_t)t * 8;
    float4 a = *(const float4*)(vw + i);
    float4 b = *(const float4*)(vw + i + 4);
    __half2 h0 = __floats2half2_rn(a.x, a.y);
    __half2 h1 = __floats2half2_rn(a.z, a.w);
    __half2 h2 = __floats2half2_rn(b.x, b.y);
    __half2 h3 = __floats2half2_rn(b.z, b.w);
    uint4 o;
    o.x = *(uint32_t*)&h0; o.y = *(uint32_t*)&h1;
    o.z = *(uint32_t*)&h2; o.w = *(uint32_t*)&h3;
    *(uint4*)(g_w16 + i) = o;
    if (t < VOCAB) g_bl2[t] = fmaf(__ldg(vb + t), L2E, 127.0f - 30.f * L2E);
    if (t < (NSLOT * ROWS) / 4) {
        float4 z = {0.f, 0.f, 0.f, 0.f};
        ((float4*)g_epsG)[t] = z;
    }
}

// ================= Kernel G1: xw[b][v][s] = W[v]·xv[b][s] (fp16, tile layout) ==========
// grid (NCHUNK, B_), 256 threads. M=128 vocab rows, N=64 states, K=128.
#define PITCH   272
#define KG1_SMEM (34816 + 17408)
__global__ __launch_bounds__(256) void kG1(const float* __restrict__ latent,
                                           const int* __restrict__ zi) {
    extern __shared__ char sm[];
    uint32_t sb = smem_u32b(sm);
    char* wS  = sm;            // 128 x 272
    char* xvS = sm + 34816;    // 64 x 272
    int c = blockIdx.x, b = blockIdx.y;
    int tid = threadIdx.x, lane = tid & 31, wid = tid >> 5;
    int warp_m = wid >> 1, warp_n = wid & 1;   // 4 x 32 rows, 2 x 32 cols

    // load W chunk (cp.async)
    const char* gw = (const char*)g_w16;
    #pragma unroll
    for (int i = 0; i < 8; i++) {
        int idx = tid + i * 256, row = idx >> 4, part = idx & 15;
        cpa16(sb + row * PITCH + part * 16, gw + ((size_t)c << 15) + ((size_t)idx << 4));
    }
    CP_COMMIT();

    // load + convert xv (fp32 -> fp16 smem)
    const float* xv = latent + (size_t)zi[16 + (b >> 2)] * 32768 + (size_t)(b & 3) * 8192;
    #pragma unroll
    for (int i = 0; i < 4; i++) {
        int idx8 = (tid + i * 256) * 8;          // 8 floats
        int srow = idx8 >> 7, e = idx8 & 127;
        float4 f0 = __ldg((const float4*)(xv + idx8));
        float4 f1 = __ldg((const float4*)(xv + idx8 + 4));
        __half2 q0 = __floats2half2_rn(f0.x, f0.y);
        __half2 q1 = __floats2half2_rn(f0.z, f0.w);
        __half2 q2 = __floats2half2_rn(f1.x, f1.y);
        __half2 q3 = __floats2half2_rn(f1.z, f1.w);
        uint4 o;
        o.x = *(uint32_t*)&q0; o.y = *(uint32_t*)&q1;
        o.z = *(uint32_t*)&q2; o.w = *(uint32_t*)&q3;
        *(uint4*)(xvS + srow * PITCH + e * 2) = o;
    }
    CP_WAIT0();
    __syncthreads();

    uint32_t aBase = sb + (uint32_t)(warp_m * 32 + (lane & 15)) * PITCH + (uint32_t)(lane >> 4) * 16;
    uint32_t bBase = sb + 34816 + (uint32_t)(warp_n * 32 + (lane & 7)) * PITCH + (uint32_t)((lane >> 3) & 1) * 16;

    uint32_t hd[2][4][2];
    #pragma unroll
    for (int mt = 0; mt < 2; mt++)
        #pragma unroll
        for (int nt = 0; nt < 4; nt++) { hd[mt][nt][0] = 0u; hd[mt][nt][1] = 0u; }

    #pragma unroll
    for (int ks = 0; ks < 8; ks++) {
        uint32_t a[2][4], bb[4][2];
        #pragma unroll
        for (int mt = 0; mt < 2; mt++)
            ldm_x4(aBase + (uint32_t)(mt * 16) * PITCH + (uint32_t)(ks * 32),
                   a[mt][0], a[mt][1], a[mt][2], a[mt][3]);
        #pragma unroll
        for (int nt = 0; nt < 4; nt++)
            ldm_x2(bBase + (uint32_t)(nt * 8) * PITCH + (uint32_t)(ks * 32),
                   bb[nt][0], bb[nt][1]);
        #pragma unroll
        for (int mt = 0; mt < 2; mt++)
            #pragma unroll
            for (int nt = 0; nt < 4; nt++)
                mma16816h(hd[mt][nt], a[mt], bb[nt]);
    }

    // store: out[(b*250+c)*128 + v][s] fp16, u32 per fragment reg (col pair contiguous)
    unsigned short* outp = g_xw16 + (((size_t)b * NCHUNK + c) << 13);   // *8192 elems
    #pragma unroll
    for (int mt = 0; mt < 2; mt++) {
        #pragma unroll
        for (int nt = 0; nt < 4; nt++) {
            int colv = warp_n * 32 + nt * 8 + (lane & 3) * 2;
            int row0 = warp_m * 32 + mt * 16 + (lane >> 2);
            *(uint32_t*)(outp + (size_t)row0 * 64 + colv)       = hd[mt][nt][0];
            *(uint32_t*)(outp + (size_t)(row0 + 8) * 64 + colv) = hd[mt][nt][1];
        }
    }
}

// ================= Kernel T: exact fp32 target logits =================
__global__ __launch_bounds__(256) void kT(const float* __restrict__ vw,
                                          const float* __restrict__ vb,
                                          const int*   __restrict__ y) {
    int r = blockIdx.x * 8 + (threadIdx.x >> 5);
    int lane = threadIdx.x & 31;
    int t = __ldg(y + r);
    float4 z = *(const float4*)(g_zs + (size_t)r * 128 + lane * 4);
    float4 w = *(const float4*)(vw + (size_t)t * 128 + lane * 4);
    float d = z.x * w.x + z.y * w.y + z.z * w.z + z.w * w.w;
    #pragma unroll
    for (int off = 16; off; off >>= 1) d += __shfl_xor_sync(0xffffffffu, d, off);
    if (lane == 0) g_tg[r] = d + __ldg(vb + t);
}

// ================= Kernel C5: persistent K=64 HMMA + poly-exp =================
#define PITCH2   144                 // 64 fp16 (128B) + 16B pad
#define SM_A2    0                   // 128 x 144 = 18432
#define SM_B02   18432               // 2 x 18432
#define SMEM_KC2 (18432 * 3)

template<bool DO_EPI>
__device__ __forceinline__ void do_chunk2(uint32_t aBase, uint32_t Bbase,
                                          uint32_t (&hdN)[4][4][2],
                                          uint32_t (&hdO)[4][4][2],
                                          const float* __restrict__ bl2c,
                                          int warp_n, int lane,
                                          const ExpC& K, u64t (&RS)[8]) {
    #pragma unroll
    for (int mt = 0; mt < 4; mt++)
        #pragma unroll
        for (int nt = 0; nt < 4; nt++) { hdN[mt][nt][0] = 0u; hdN[mt][nt][1] = 0u; }

    u64t bv[4];
    if (DO_EPI) {
        #pragma unroll
        for (int nt = 0; nt < 4; nt++)
            bv[nt] = *(const u64t*)&bl2c[warp_n * 32 + nt * 8 + (lane & 3) * 2];
    }

    #pragma unroll
    for (int ks = 0; ks < 4; ks++) {
        uint32_t a[4][4], b[4][2];
        #pragma unroll
        for (int mt = 0; mt < 4; mt++)
            ldm_x4(aBase + (uint32_t)(mt * 16) * PITCH2 + (uint32_t)(ks * 32),
                   a[mt][0], a[mt][1], a[mt][2], a[mt][3]);
        #pragma unroll
        for (int nt = 0; nt < 4; nt++)
            ldm_x2(Bbase + (uint32_t)(nt * 8) * PITCH2 + (uint32_t)(ks * 32),
                   b[nt][0], b[nt][1]);
        #pragma unroll
        for (int mt = 0; mt < 4; mt++)
            #pragma unroll
            for (int nt = 0; nt < 4; nt++)
                mma16816h(hdN[mt][nt], a[mt], b[nt]);
        if (DO_EPI) {
            // 4 fragments of the OLD chunk per ks (16 total over 4 ks)
            #pragma unroll
            for (int f = ks * 4; f < ks * 4 + 4; f++) {
                int mt = f >> 2, nt = f & 3;
                expacc2(h2f2(hdO[mt][nt][0]), bv[nt], K, RS[mt * 2 + 0]);
                expacc2(h2f2(hdO[mt][nt][1]), bv[nt], K, RS[mt * 2 + 1]);
            }
        }
    }
}

__device__ __forceinline__ void epi_only2(uint32_t (&hdO)[4][4][2],
                                          const float* __restrict__ bl2c,
                                          int warp_n, int lane,
                                          const ExpC& K, u64t (&RS)[8]) {
    #pragma unroll
    for (int nt = 0; nt < 4; nt++) {
        u64t bv = *(const u64t*)&bl2c[warp_n * 32 + nt * 8 + (lane & 3) * 2];
        #pragma unroll
        for (int mt = 0; mt < 4; mt++) {
            expacc2(h2f2(hdO[mt][nt][0]), bv, K, RS[mt * 2 + 0]);
            expacc2(h2f2(hdO[mt][nt][1]), bv, K, RS[mt * 2 + 1]);
        }
    }
}

__global__ __launch_bounds__(256, 1) void kC5() {
    extern __shared__ char sm[];
    uint32_t sb = smem_u32b(sm);
    int tid = threadIdx.x, lane = tid & 31, wid = tid >> 5;
    int warp_m = wid >> 2, warp_n = wid & 3;

    const char* ga = (const char*)g_a16;
    const char* gx = (const char*)g_xw16;

    ExpC K;
    K.L2E2 = pk2(L2E, L2E);
    K.MG2  = pk2(12582912.0f, 12582912.0f);
    K.NEG1 = pk2(-1.0f, -1.0f);
    K.C4   = pk2(0.009618129107f, 0.009618129107f);
    K.C3   = pk2(0.055504108664f, 0.055504108664f);
    K.C2   = pk2(0.240226506959f, 0.240226506959f);
    K.C1   = pk2(0.693147180560f, 0.693147180560f);
    K.ONE2 = pk2(1.0f, 1.0f);

    uint32_t aBase = sb + SM_A2 + (uint32_t)(warp_m * 64 + (lane & 15)) * PITCH2 + (uint32_t)(lane >> 4) * 16;
    uint32_t bRowOff = (uint32_t)(warp_n * 32 + (lane & 7)) * PITCH2 + (uint32_t)((lane >> 3) & 1) * 16;

    int cta = blockIdx.x;
    int u0 = (cta * NUNITS) / NCTA;
    int u1 = ((cta + 1) * NUNITS) / NCTA;

    uint32_t hdA[4][4][2], hdB[4][4][2];
    u64t RS[8];

    int u = u0;
    while (u < u1) {
        int mt   = u / NGRP;                      // mtile 0..63; batch = mt>>1
        int uend = min(u1, (mt + 1) * NGRP);
        int g0   = u - mt * NGRP;
        int ch0  = g0 * GRP;
        int nch  = (uend - mt * NGRP) * GRP - ch0;
        size_t xwbase = (((size_t)(mt >> 1) * NCHUNK) << 14);   // byte base of this batch's tiles

        #pragma unroll
        for (int k = 0; k < 8; k++) RS[k] = 0ULL;

        // segment prologue: A tile (16KB) + B(ch0) -> buf0; B(ch0+1) -> buf1
        #pragma unroll
        for (int i = 0; i < 4; i++) {
            int idx = tid + i * 256, row = idx >> 3, part = idx & 7;
            cpa16(sb + SM_A2 + row * PITCH2 + part * 16,
                  ga + ((size_t)mt << 14) + ((size_t)idx << 4));
        }
        #pragma unroll
        for (int i = 0; i < 4; i++) {
            int idx = tid + i * 256, row = idx >> 3, part = idx & 7;
            cpa16(sb + SM_B02 + row * PITCH2 + part * 16,
                  gx + xwbase + ((size_t)ch0 << 14) + ((size_t)idx << 4));
        }
        CP_COMMIT();
        #pragma unroll
        for (int i = 0; i < 4; i++) {
            int idx = tid + i * 256, row = idx >> 3, part = idx & 7;
            cpa16(sb + SM_B02 + 18432 + row * PITCH2 + part * 16,
                  gx + xwbase + ((size_t)(ch0 + 1) << 14) + ((size_t)idx << 4));
        }
        CP_COMMIT();

        CP_WAIT1();
        __syncthreads();
        do_chunk2<false>(aBase, sb + SM_B02 + bRowOff, hdA, hdB, g_bl2, warp_n, lane, K, RS);
        __syncthreads();
        if (2 < nch) {
            #pragma unroll
            for (int i = 0; i < 4; i++) {
                int idx = tid + i * 256, row = idx >> 3, part = idx & 7;
                cpa16(sb + SM_B02 + row * PITCH2 + part * 16,
                      gx + xwbase + ((size_t)(ch0 + 2) << 14) + ((size_t)idx << 4));
            }
        }
        CP_COMMIT();

        #pragma unroll 1
        for (int c = 0; c < nch; c++) {
            int p = c & 1;
            const float* bl2c = g_bl2 + (size_t)(ch0 + c) * 128;
            if (c + 1 < nch) {
                CP_WAIT1();
                __syncthreads();
                uint32_t Bb = sb + SM_B02 + (uint32_t)(p ^ 1) * 18432 + bRowOff;
                if (p == 0) do_chunk2<true>(aBase, Bb, hdB, hdA, bl2c, warp_n, lane, K, RS);
                else        do_chunk2<true>(aBase, Bb, hdA, hdB, bl2c, warp_n, lane, K, RS);
                __syncthreads();
                if (c + 3 < nch) {
                    #pragma unroll
                    for (int i = 0; i < 4; i++) {
                        int idx = tid + i * 256, row = idx >> 3, part = idx & 7;
                        cpa16(sb + SM_B02 + (uint32_t)(p ^ 1) * 18432 + row * PITCH2 + part * 16,
                              gx + xwbase + ((size_t)(ch0 + c + 3) << 14) + ((size_t)idx << 4));
                    }
                }
                CP_COMMIT();
            } else {
                if (p == 0) epi_only2(hdA, bl2c, warp_n, lane, K, RS);
                else        epi_only2(hdB, bl2c, warp_n, lane, K, RS);
            }
        }

        // deterministic flush: slot = (g0, warp_n)
        #pragma unroll
        for (int k = 0; k < 8; k++) {
            float lo, hi;
            asm("mov.b64 {%0, %1}, %2;" : "=f"(lo), "=f"(hi) : "l"(RS[k]));
            float s = lo + hi;
            s += __shfl_xor_sync(0xffffffffu, s, 1);
            s += __shfl_xor_sync(0xffffffffu, s, 2);
            if ((lane & 3) == 0) {
                int mtt = k >> 1, rp = k & 1;
                int row = mt * 128 + warp_m * 64 + mtt * 16 + (lane >> 2) + rp * 8;
                g_epsG[(size_t)(g0 * 4 + warp_n) * ROWS + row] = s;
            }
        }
        u = uend;
    }
}

// ================= Kernel F: merge =================
__global__ void kF(float* __restrict__ out) {
    int r = blockIdx.x * 256 + threadIdx.x;
    float se = 0.f;
    #pragma unroll 4
    for (int s = 0; s < NSLOT; s++) se += g_epsG[(size_t)s * ROWS + r];
    out[r] = g_tg[r] - 30.f - logf(se);
}

// ================= launch =================
extern "C" void kernel_launch(void* const* d_in, const int* in_sizes, int n_in,
                              void* d_out, int out_size) {
    const float* latent = (const float*)d_in[0];
    const float* vw     = (const float*)d_in[1];
    const float* vb     = (const float*)d_in[2];
    const int*   zi     = (const int*)d_in[3];
    const int*   y      = (const int*)d_in[4];
    float* out = (float*)d_out;

    static cudaStream_t s1 = nullptr;
    static cudaEvent_t e0, eW, eZ, eT;
    if (!s1) {
        cudaStreamCreateWithFlags(&s1, cudaStreamNonBlocking);
        cudaEventCreateWithFlags(&e0, cudaEventDisableTiming);
        cudaEventCreateWithFlags(&eW, cudaEventDisableTiming);
        cudaEventCreateWithFlags(&eZ, cudaEventDisableTiming);
        cudaEventCreateWithFlags(&eT, cudaEventDisableTiming);
        cudaFuncSetAttribute(kA12, cudaFuncAttributeMaxDynamicSharedMemorySize, KA12_SMEM);
        cudaFuncSetAttribute(kB1v3, cudaFuncAttributeMaxDynamicSharedMemorySize, KB1_SMEM);
        cudaFuncSetAttribute(kG1, cudaFuncAttributeMaxDynamicSharedMemorySize, KG1_SMEM);
        cudaFuncSetAttribute(kC5, cudaFuncAttributeMaxDynamicSharedMemorySize, SMEM_KC2);
    }

    // side stream: vocab fp16 + bl2 + eps zero, then first GEMM xv·W^T (overlaps scan chain)
    cudaEventRecord(e0, 0);
    cudaStreamWaitEvent(s1, e0, 0);
    kWc<<<2000, 256, 0, s1>>>(vw, vb);
    kG1<<<dim3(NCHUNK, B_), 256, KG1_SMEM, s1>>>(latent, zi);
    cudaEventRecord(eW, s1);

    // main chain: attention prep -> scan -> zs + A fp16
    kA12<<<B_, 256, KA12_SMEM>>>(latent, zi);
    kB1v3<<<B_, 512, KB1_SMEM>>>();
    kB2<<<256, 256>>>(latent, zi);

    // fork: exact target logits (overlaps kC5)
    cudaEventRecord(eZ, 0);
    cudaStreamWaitEvent(s1, eZ, 0);
    kT<<<1024, 256, 0, s1>>>(vw, vb, y);
    cudaEventRecord(eT, s1);

    // join side chain, run K=64 persistent fused GEMM
    cudaStreamWaitEvent(0, eW, 0);
    kC5<<<NCTA, 256, SMEM_KC2>>>();

    cudaStreamWaitEvent(0, eT, 0);
    kF<<<32, 256>>>(out);
}